// round 12
// baseline (speedup 1.0000x reference)
#include <cuda_runtime.h>

// Sparsemax over last axis: x [16, 2048, 1024] fp32. 32768 rows of N=1024.
//
// Converged base (R2-R11): one WARP per row, 32 values/thread in registers,
// shuffle-only reductions, 128-thread CTAs (grid 8192), natural register
// allocation (48 regs -> 40 warps/SM), non-persistent launch.
//
// R12 single-variable probe: __ldcs/__stcs streaming hints ONLY on top of
// the converged base. Rationale: R4 (occ6+hints+fdiv, 40.4us) beat R6
// (occ6 alone, 41.6us) at equal occupancy -> hints were possibly a small
// WIN previously masked by the occupancy regression they were bundled with.
// Mechanism: both streams are touched exactly once; evict-first stops dead
// read lines from competing with the write stream in L2.
//
// Threshold tau* solves sum_i max(x_i - tau, 0) = 1. Fixed-point iteration
// tau <- (sum_{x>tau} x - 1) / count_{x>tau}, seeded at tau0 = max(x) - 1
// (lower bound on tau*; support ~14 elems -> ~3-4 iterations). Monotone
// ascent to the exact fp32 fixed point; count >= 1 since tau < max(x)
// throughout; warp-uniform termination.

#define ROW_N   1024
#define VPT     32            // values per thread
#define WPB     4             // warps (rows) per block
#define THREADS (WPB * 32)

__device__ __forceinline__ float warp_sum(float v) {
#pragma unroll
    for (int o = 16; o; o >>= 1) v += __shfl_xor_sync(0xffffffffu, v, o);
    return v;
}

__device__ __forceinline__ float warp_max(float v) {
#pragma unroll
    for (int o = 16; o; o >>= 1) v = fmaxf(v, __shfl_xor_sync(0xffffffffu, v, o));
    return v;
}

__global__ __launch_bounds__(THREADS)
void sparsemax_kernel(const float* __restrict__ x, float* __restrict__ out) {
    const int lane = threadIdx.x & 31;
    const int wid  = threadIdx.x >> 5;
    const size_t row = (size_t)blockIdx.x * WPB + wid;

    const float4* __restrict__ xr =
        reinterpret_cast<const float4*>(x) + row * (ROW_N / 4);

    float va[VPT];
    float m = -3.402823466e+38f;
#pragma unroll
    for (int k = 0; k < VPT / 4; ++k) {
        float4 f = __ldcs(xr + k * 32 + lane);   // streaming read (touched once)
        va[4 * k + 0] = f.x;
        va[4 * k + 1] = f.y;
        va[4 * k + 2] = f.z;
        va[4 * k + 3] = f.w;
        m = fmaxf(m, fmaxf(fmaxf(f.x, f.y), fmaxf(f.z, f.w)));
    }

    // tight lower start: tau* >= max - 1
    m = warp_max(m);
    float tau = m - 1.0f;

    // fixed-point iterations (warp-independent, exact fp32 fixed point)
#pragma unroll 1
    for (int it = 0; it < 32; ++it) {
        float ps = 0.f, pc = 0.f;
#pragma unroll
        for (int i = 0; i < VPT; ++i) {
            if (va[i] > tau) { ps += va[i]; pc += 1.f; }
        }
        ps = warp_sum(ps);
        pc = warp_sum(pc);
        float ntau = (ps - 1.0f) / pc;
        if (ntau == tau) break;   // warp-uniform (identical reduce order)
        tau = ntau;
    }

    float4* __restrict__ orow =
        reinterpret_cast<float4*>(out) + row * (ROW_N / 4);
#pragma unroll
    for (int k = 0; k < VPT / 4; ++k) {
        float4 o;
        o.x = fmaxf(va[4 * k + 0] - tau, 0.0f);
        o.y = fmaxf(va[4 * k + 1] - tau, 0.0f);
        o.z = fmaxf(va[4 * k + 2] - tau, 0.0f);
        o.w = fmaxf(va[4 * k + 3] - tau, 0.0f);
        __stcs(orow + k * 32 + lane, o);         // streaming write
    }
}

extern "C" void kernel_launch(void* const* d_in, const int* in_sizes, int n_in,
                              void* d_out, int out_size) {
    const float* x = (const float*)d_in[0];
    float* out = (float*)d_out;
    const int rows = in_sizes[0] / ROW_N;   // 32768
    sparsemax_kernel<<<rows / WPB, THREADS>>>(x, out);
}

// round 13
// speedup vs baseline: 1.0360x; 1.0360x over previous
#include <cuda_runtime.h>

// Sparsemax over last axis: x [16, 2048, 1024] fp32. 32768 rows of N=1024.
//
// FINAL — converged optimum, reproduced 5x (R3/R7/R8/R9/R10/R11):
//   - one WARP per row, 32 values/thread in registers, shuffle-only
//     reductions (no smem, no block syncs)
//   - 128-thread CTAs, grid 8192, non-persistent (persistent: -10%)
//   - natural register allocation (48 regs -> 40 warps/SM; forcing 6
//     blocks/SM lowers DRAM BW ~8% via cross-CTA L1tex-queue contention)
//   - plain ld/st (.cs streaming hints measured exactly neutral in
//     isolation, R12; __fdividef neutral)
//
// Threshold tau* solves sum_i max(x_i - tau, 0) = 1. Fixed-point iteration
// tau <- (sum_{x>tau} x - 1) / count_{x>tau}, seeded at tau0 = max(x) - 1
// (always a lower bound on tau*; starting support ~14 elems for gaussian
// rows -> ~3-4 iterations). Monotone ascent to the exact fp32 fixed point;
// count >= 1 at every iterate since tau < max(x) throughout; warp-uniform
// termination (identical reduce order on all lanes).
//
// At the HBM floor: 256 MB mandatory read+write (dense output — zeros must
// be written). Kernel-window DRAM ~74%, issue ~60% (fully hidden). Repeat
// benches of this identical binary span 43.5-45.5 us = clock envelope.

#define ROW_N   1024
#define VPT     32            // values per thread
#define WPB     4             // warps (rows) per block
#define THREADS (WPB * 32)

__device__ __forceinline__ float warp_sum(float v) {
#pragma unroll
    for (int o = 16; o; o >>= 1) v += __shfl_xor_sync(0xffffffffu, v, o);
    return v;
}

__device__ __forceinline__ float warp_max(float v) {
#pragma unroll
    for (int o = 16; o; o >>= 1) v = fmaxf(v, __shfl_xor_sync(0xffffffffu, v, o));
    return v;
}

__global__ __launch_bounds__(THREADS)
void sparsemax_kernel(const float* __restrict__ x, float* __restrict__ out) {
    const int lane = threadIdx.x & 31;
    const int wid  = threadIdx.x >> 5;
    const size_t row = (size_t)blockIdx.x * WPB + wid;

    const float4* __restrict__ xr =
        reinterpret_cast<const float4*>(x) + row * (ROW_N / 4);

    float va[VPT];
    float m = -3.402823466e+38f;
#pragma unroll
    for (int k = 0; k < VPT / 4; ++k) {
        float4 f = xr[k * 32 + lane];       // coalesced: 32 lanes x 16B
        va[4 * k + 0] = f.x;
        va[4 * k + 1] = f.y;
        va[4 * k + 2] = f.z;
        va[4 * k + 3] = f.w;
        m = fmaxf(m, fmaxf(fmaxf(f.x, f.y), fmaxf(f.z, f.w)));
    }

    // tight lower start: tau* >= max - 1
    m = warp_max(m);
    float tau = m - 1.0f;

    // fixed-point iterations (warp-independent, exact fp32 fixed point)
#pragma unroll 1
    for (int it = 0; it < 32; ++it) {
        float ps = 0.f, pc = 0.f;
#pragma unroll
        for (int i = 0; i < VPT; ++i) {
            if (va[i] > tau) { ps += va[i]; pc += 1.f; }
        }
        ps = warp_sum(ps);
        pc = warp_sum(pc);
        float ntau = (ps - 1.0f) / pc;
        if (ntau == tau) break;   // warp-uniform (identical reduce order)
        tau = ntau;
    }

    float4* __restrict__ orow =
        reinterpret_cast<float4*>(out) + row * (ROW_N / 4);
#pragma unroll
    for (int k = 0; k < VPT / 4; ++k) {
        float4 o;
        o.x = fmaxf(va[4 * k + 0] - tau, 0.0f);
        o.y = fmaxf(va[4 * k + 1] - tau, 0.0f);
        o.z = fmaxf(va[4 * k + 2] - tau, 0.0f);
        o.w = fmaxf(va[4 * k + 3] - tau, 0.0f);
        orow[k * 32 + lane] = o;
    }
}

extern "C" void kernel_launch(void* const* d_in, const int* in_sizes, int n_in,
                              void* d_out, int out_size) {
    const float* x = (const float*)d_in[0];
    float* out = (float*)d_out;
    const int rows = in_sizes[0] / ROW_N;   // 32768
    sparsemax_kernel<<<rows / WPB, THREADS>>>(x, out);
}